// round 15
// baseline (speedup 1.0000x reference)
#include <cuda_runtime.h>

#define NNODES 20000
#define DEG 16
#define S 17
#define T 10
#define M 10
#define D 128
#define N_OUTER 5
#define N_SINK 15
#define RPAD 12     // 10 padded to 12 (48B rows, 16B-aligned)
#define KTPAD 36    // KT staging rows: 144B stride -> conflict-free LDS.128 gather

typedef unsigned long long u64;

// ---- packed f32x2 helpers (sm_100+) ----
__device__ __forceinline__ u64 pk(float lo, float hi) {
    u64 r; asm("mov.b64 %0,{%1,%2};" : "=l"(r) : "f"(lo), "f"(hi)); return r;
}
__device__ __forceinline__ void upk(float& lo, float& hi, u64 v) {
    asm("mov.b64 {%0,%1},%2;" : "=f"(lo), "=f"(hi) : "l"(v));
}
__device__ __forceinline__ u64 f2fma(u64 a, u64 b, u64 c) {
    u64 d; asm("fma.rn.f32x2 %0,%1,%2,%3;" : "=l"(d) : "l"(a), "l"(b), "l"(c)); return d;
}
__device__ __forceinline__ u64 f2mul(u64 a, u64 b) {
    u64 d; asm("mul.rn.f32x2 %0,%1,%2;" : "=l"(d) : "l"(a), "l"(b)); return d;
}
__device__ __forceinline__ u64 f2add(u64 a, u64 b) {
    u64 d; asm("add.rn.f32x2 %0,%1,%2;" : "=l"(d) : "l"(a), "l"(b)); return d;
}
// width-16 shuffle of a packed u64 (per-half broadcast)
__device__ __forceinline__ u64 shfl64h(u64 v, int src) {
    return (u64)__shfl_sync(0xffffffffu, (unsigned long long)v, src, 16);
}

// Precomputed: XFP[n][t][m] = ||F2[t][m]||^2 - 2 x[n].F2[t][m],  NX[n] = ||x[n]||^2
__device__ float g_XFP[(long)NNODES * T * RPAD];
__device__ float g_NX[NNODES];

__global__ __launch_bounds__(128)
void xf2_kernel(const float* __restrict__ x, const float* __restrict__ F2g)
{
    __shared__ float sx[4][D];
    const int tid = threadIdx.x;
    const int nbase = blockIdx.x * 4;
#pragma unroll
    for (int i = 0; i < 4; i++)
        sx[i][tid] = x[(long)(nbase + i) * D + tid];
    __syncthreads();

    if (tid < T * M) {
        const float* f2 = F2g + tid * D;
        float a0 = 0.f, a1 = 0.f, a2 = 0.f, a3 = 0.f, nf = 0.f;
#pragma unroll 8
        for (int c = 0; c < D / 4; c++) {
            float4 f = __ldg((const float4*)(f2 + 4 * c));
            nf = fmaf(f.x, f.x, fmaf(f.y, f.y, fmaf(f.z, f.z, fmaf(f.w, f.w, nf))));
            float4 x0 = *(const float4*)&sx[0][4 * c];
            a0 = fmaf(f.x, x0.x, fmaf(f.y, x0.y, fmaf(f.z, x0.z, fmaf(f.w, x0.w, a0))));
            float4 x1 = *(const float4*)&sx[1][4 * c];
            a1 = fmaf(f.x, x1.x, fmaf(f.y, x1.y, fmaf(f.z, x1.z, fmaf(f.w, x1.w, a1))));
            float4 x2 = *(const float4*)&sx[2][4 * c];
            a2 = fmaf(f.x, x2.x, fmaf(f.y, x2.y, fmaf(f.z, x2.z, fmaf(f.w, x2.w, a2))));
            float4 x3 = *(const float4*)&sx[3][4 * c];
            a3 = fmaf(f.x, x3.x, fmaf(f.y, x3.y, fmaf(f.z, x3.z, fmaf(f.w, x3.w, a3))));
        }
        const int t = tid / M, m = tid % M;
        g_XFP[((long)(nbase + 0) * T + t) * RPAD + m] = nf - 2.f * a0;
        g_XFP[((long)(nbase + 1) * T + t) * RPAD + m] = nf - 2.f * a1;
        g_XFP[((long)(nbase + 2) * T + t) * RPAD + m] = nf - 2.f * a2;
        g_XFP[((long)(nbase + 3) * T + t) * RPAD + m] = nf - 2.f * a3;
    } else if (tid < T * M + 4) {
        const int nn = tid - T * M;
        float a = 0.f;
#pragma unroll 8
        for (int c = 0; c < D / 4; c++) {
            float4 v = *(const float4*)&sx[nn][4 * c];
            a = fmaf(v.x, v.x, fmaf(v.y, v.y, fmaf(v.z, v.z, fmaf(v.w, v.w, a))));
        }
        g_NX[nbase + nn] = a;
    }
}

// Fused tens for TWO rows of the same template. C2w holds (-2*C2).
__device__ __forceinline__ void tens_pair(const float* Pw, const float* C2w,
                                          const float* c2qw,
                                          unsigned mka, unsigned mkb,
                                          float c1pa, float c1pb,
                                          u64* ta, u64* tb)
{
    u64 Aa0 = 0, Aa1 = 0, Aa2 = 0, Aa3 = 0, Aa4 = 0;
    u64 Ab0 = 0, Ab1 = 0, Ab2 = 0, Ab3 = 0, Ab4 = 0;
#pragma unroll
    for (int uu = 0; uu < S; uu++) {
        const float* pr = Pw + uu * RPAD;
        ulonglong2 r01 = *(const ulonglong2*)pr;
        ulonglong2 r23 = *(const ulonglong2*)(pr + 4);
        u64 r4 = *(const u64*)(pr + 8);
        unsigned ba = (mka >> uu) & 1u;
        unsigned bb = (mkb >> uu) & 1u;
        asm("{\n\t.reg .pred pa,pb;\n\t"
            "setp.ne.u32 pa,%10,0;\n\t"
            "setp.ne.u32 pb,%11,0;\n\t"
            "@pa add.rn.f32x2 %0,%0,%12;\n\t"
            "@pa add.rn.f32x2 %1,%1,%13;\n\t"
            "@pa add.rn.f32x2 %2,%2,%14;\n\t"
            "@pa add.rn.f32x2 %3,%3,%15;\n\t"
            "@pa add.rn.f32x2 %4,%4,%16;\n\t"
            "@pb add.rn.f32x2 %5,%5,%12;\n\t"
            "@pb add.rn.f32x2 %6,%6,%13;\n\t"
            "@pb add.rn.f32x2 %7,%7,%14;\n\t"
            "@pb add.rn.f32x2 %8,%8,%15;\n\t"
            "@pb add.rn.f32x2 %9,%9,%16;\n\t}"
            : "+l"(Aa0), "+l"(Aa1), "+l"(Aa2), "+l"(Aa3), "+l"(Aa4),
              "+l"(Ab0), "+l"(Ab1), "+l"(Ab2), "+l"(Ab3), "+l"(Ab4)
            : "r"(ba), "r"(bb),
              "l"(r01.x), "l"(r01.y), "l"(r23.x), "l"(r23.y), "l"(r4));
    }
    {
        u64 ca2 = pk(c1pa, c1pa);
        u64 cb2 = pk(c1pb, c1pb);
        ulonglong2 cq01 = *(const ulonglong2*)c2qw;
        ulonglong2 cq23 = *(const ulonglong2*)(c2qw + 4);
        u64 cq4 = *(const u64*)(c2qw + 8);
        ta[0] = f2add(ca2, cq01.x); tb[0] = f2add(cb2, cq01.x);
        ta[1] = f2add(ca2, cq01.y); tb[1] = f2add(cb2, cq01.y);
        ta[2] = f2add(ca2, cq23.x); tb[2] = f2add(cb2, cq23.x);
        ta[3] = f2add(ca2, cq23.y); tb[3] = f2add(cb2, cq23.y);
        ta[4] = f2add(ca2, cq4);    tb[4] = f2add(cb2, cq4);
    }
    float aav[M], abv[M];
    upk(aav[0], aav[1], Aa0); upk(aav[2], aav[3], Aa1); upk(aav[4], aav[5], Aa2);
    upk(aav[6], aav[7], Aa3); upk(aav[8], aav[9], Aa4);
    upk(abv[0], abv[1], Ab0); upk(abv[2], abv[3], Ab1); upk(abv[4], abv[5], Ab2);
    upk(abv[6], abv[7], Ab3); upk(abv[8], abv[9], Ab4);
#pragma unroll
    for (int v = 0; v < M; v++) {
        u64 ava2 = pk(aav[v], aav[v]);
        u64 avb2 = pk(abv[v], abv[v]);
        const float* c2r = C2w + v * RPAD;
        ulonglong2 c01 = *(const ulonglong2*)c2r;
        ulonglong2 c23 = *(const ulonglong2*)(c2r + 4);
        u64 c4 = *(const u64*)(c2r + 8);
        ta[0] = f2fma(ava2, c01.x, ta[0]); tb[0] = f2fma(avb2, c01.x, tb[0]);
        ta[1] = f2fma(ava2, c01.y, ta[1]); tb[1] = f2fma(avb2, c01.y, tb[1]);
        ta[2] = f2fma(ava2, c23.x, ta[2]); tb[2] = f2fma(avb2, c23.x, tb[2]);
        ta[3] = f2fma(ava2, c23.y, ta[3]); tb[3] = f2fma(avb2, c23.y, tb[3]);
        ta[4] = f2fma(ava2, c4,    ta[4]); tb[4] = f2fma(avb2, c4,    tb[4]);
    }
}

// 160 threads = 5 warps; warp ww serves templates 2ww (lanes 0-15) and 2ww+1 (lanes 16-31).
// Each lane owns rows ra=2*hl, rb=2*hl+1 (hl = lane % 16).
__global__ __launch_bounds__(160, 5)
void ltfgw_kernel(const int* __restrict__ edge_dst,
                  const float* __restrict__ C2g,
                  const float* __restrict__ q0,
                  const float* __restrict__ alpha0,
                  float* __restrict__ out)
{
    __shared__ __align__(16) int      sNodes[S];
    __shared__ __align__(16) unsigned sMask[S];
    __shared__ __align__(16) float    sQ[RPAD];
    __shared__ __align__(16) float    sC2[T][M][RPAD];    // holds -2*C2
    __shared__ __align__(16) float    sC2q[T][RPAD];
    __shared__ __align__(16) float    sP[T][S][RPAD];
    __shared__ __align__(16) float    sKT[T][M][KTPAD];   // transposed K staging (per outer)
    __shared__ __align__(16) float    sV[T][RPAD];

    const int n    = blockIdx.x;
    const int tid  = threadIdx.x;
    const int ww   = tid >> 5;
    const int lane = tid & 31;
    const int half = lane >> 4;
    const int hl   = lane & 15;
    const int t    = 2 * ww + half;
    const int ra   = 2 * hl;
    const int rb   = ra + 1;
    const bool aa  = (ra < S);   // hl <= 8
    const bool ab  = (rb < S);   // hl <= 7
    const bool vm  = (hl < M);

    if (tid < S) sNodes[tid] = (tid == 0) ? n : edge_dst[n * DEG + tid - 1];
    if (tid == 0) {
        float qq[M];
        float mxq = -1e30f;
#pragma unroll
        for (int m = 0; m < M; m++) { qq[m] = q0[m]; mxq = fmaxf(mxq, qq[m]); }
        float ssum = 0.f;
#pragma unroll
        for (int m = 0; m < M; m++) { qq[m] = __expf(qq[m] - mxq); ssum += qq[m]; }
        float inv = 1.f / ssum;
#pragma unroll
        for (int m = 0; m < M; m++) sQ[m] = qq[m] * inv;
        sQ[10] = 0.f; sQ[11] = 0.f;
    }
    __syncthreads();

    // C1 bitmask (warp 0)
    if (ww == 0) {
        int nodesr[S];
#pragma unroll
        for (int i = 0; i < S; i++) nodesr[i] = sNodes[i];
        unsigned msk0 = 0;
        if (lane < S) {
            int me = nodesr[lane];
#pragma unroll
            for (int kk = 0; kk < DEG / 4; kk++) {
                int4 nb4 = *(const int4*)(edge_dst + me * DEG + kk * 4);
                int nbs[4] = { nb4.x, nb4.y, nb4.z, nb4.w };
#pragma unroll
                for (int j = 0; j < 4; j++) {
#pragma unroll
                    for (int s2 = 0; s2 < S; s2++)
                        if (nbs[j] == nodesr[s2]) msk0 |= 1u << s2;
                }
            }
        }
        unsigned add = 0;
#pragma unroll
        for (int s2 = 0; s2 < S; s2++) {
            unsigned col = __ballot_sync(0xffffffffu, (msk0 >> s2) & 1u);
            if (lane == s2) add = col;
        }
        msk0 |= add & 0x1FFFFu;
        if (lane < S) sMask[lane] = msk0;
    }

    // C2 staging: store -2*C2; compute sC2q from raw values + sQ
    if (vm) {
        float acc = 0.f;
#pragma unroll
        for (int r = 0; r < M; r++) {
            float c = __ldg(C2g + (t * M + r) * M + hl);
            sC2[t][r][hl] = -2.f * c;
        }
#pragma unroll
        for (int b = 0; b < M; b++) {
            float c = __ldg(C2g + (t * M + hl) * M + b);
            acc = fmaf(c * c, sQ[b], acc);
        }
        sC2q[t][hl] = acc;
    }
    if (hl >= M && hl < RPAD) sC2q[t][hl] = 0.f;

    // BARRIER before any thread reads sMask (written by warp 0 only).
    __syncthreads();

    const int nodea = aa ? sNodes[ra] : 0;
    const int nodeb = ab ? sNodes[rb] : 0;
    const int offa = (nodea * T + t) * RPAD;
    const int offb = (nodeb * T + t) * RPAD;
    const float nxa = aa ? __ldg(g_NX + nodea) : 0.f;
    const float nxb = ab ? __ldg(g_NX + nodeb) : 0.f;

    const float alpha = 1.f / (1.f + __expf(-__ldg(alpha0 + n)));
    const float a1c = 1.f - alpha;
    const float a2c = 2.f * alpha;
    const float p = 1.f / 17.f;
    const unsigned mka = aa ? sMask[ra] : 0u;
    const unsigned mkb = ab ? sMask[rb] : 0u;
    const float c1pa = (float)__popc(mka) * (1.f / 17.f);
    const float c1pb = (float)__popc(mkb) * (1.f / 17.f);
    const float qm = vm ? sQ[hl] : 0.f;

    // plan0 = p (x) q
    {
        ulonglong2 qab = *(const ulonglong2*)&sQ[0];
        ulonglong2 qcd = *(const ulonglong2*)&sQ[4];
        u64 qc = *(const u64*)&sQ[8];
        u64 p2 = pk(p, p);
        if (aa) {
            ulonglong2 o; o.x = f2mul(p2, qab.x); o.y = f2mul(p2, qab.y);
            *(ulonglong2*)&sP[t][ra][0] = o;
            ulonglong2 o2; o2.x = f2mul(p2, qcd.x); o2.y = f2mul(p2, qcd.y);
            *(ulonglong2*)&sP[t][ra][4] = o2;
            *(u64*)&sP[t][ra][8] = f2mul(p2, qc);
        }
        if (ab) {
            ulonglong2 o; o.x = f2mul(p2, qab.x); o.y = f2mul(p2, qab.y);
            *(ulonglong2*)&sP[t][rb][0] = o;
            ulonglong2 o2; o2.x = f2mul(p2, qcd.x); o2.y = f2mul(p2, qcd.y);
            *(ulonglong2*)&sP[t][rb][4] = o2;
            *(u64*)&sP[t][rb][8] = f2mul(p2, qc);
        }
    }
    __syncwarp();

    u64 K2a[5], K2b[5];
    u64 KT2[8]; float kt16 = 0.f;
#pragma unroll
    for (int j = 0; j < 8; j++) KT2[j] = 0;
    float ua = 0.f, ub = 0.f;

#pragma unroll 1
    for (int outer = 0; outer < N_OUTER; outer++) {
        u64 ta[5], tb[5];
        tens_pair(&sP[t][0][0], &sC2[t][0][0], &sC2q[t][0],
                  mka, mkb, c1pa, c1pb, ta, tb);

        // G rows, eps from |G| mean over template, K = exp(-G/eps - mx)
        float Ga[M], Gb[M];
#pragma unroll
        for (int m = 0; m < M; m++) { Ga[m] = 0.f; Gb[m] = 0.f; }
        {
            u64 a1c2 = pk(a1c, a1c);
            u64 a2c2 = pk(a2c, a2c);
            if (aa) {
                u64 nxa2 = pk(nxa, nxa);
                ulonglong2 x01 = __ldg((const ulonglong2*)(g_XFP + offa));
                ulonglong2 x23 = __ldg((const ulonglong2*)(g_XFP + offa + 4));
                u64 x4 = __ldg((const u64*)(g_XFP + offa + 8));
                u64 g;
                g = f2fma(a2c2, ta[0], f2mul(a1c2, f2add(nxa2, x01.x))); upk(Ga[0], Ga[1], g);
                g = f2fma(a2c2, ta[1], f2mul(a1c2, f2add(nxa2, x01.y))); upk(Ga[2], Ga[3], g);
                g = f2fma(a2c2, ta[2], f2mul(a1c2, f2add(nxa2, x23.x))); upk(Ga[4], Ga[5], g);
                g = f2fma(a2c2, ta[3], f2mul(a1c2, f2add(nxa2, x23.y))); upk(Ga[6], Ga[7], g);
                g = f2fma(a2c2, ta[4], f2mul(a1c2, f2add(nxa2, x4)));    upk(Ga[8], Ga[9], g);
            }
            if (ab) {
                u64 nxb2 = pk(nxb, nxb);
                ulonglong2 x01 = __ldg((const ulonglong2*)(g_XFP + offb));
                ulonglong2 x23 = __ldg((const ulonglong2*)(g_XFP + offb + 4));
                u64 x4 = __ldg((const u64*)(g_XFP + offb + 8));
                u64 g;
                g = f2fma(a2c2, tb[0], f2mul(a1c2, f2add(nxb2, x01.x))); upk(Gb[0], Gb[1], g);
                g = f2fma(a2c2, tb[1], f2mul(a1c2, f2add(nxb2, x01.y))); upk(Gb[2], Gb[3], g);
                g = f2fma(a2c2, tb[2], f2mul(a1c2, f2add(nxb2, x23.x))); upk(Gb[4], Gb[5], g);
                g = f2fma(a2c2, tb[3], f2mul(a1c2, f2add(nxb2, x23.y))); upk(Gb[6], Gb[7], g);
                g = f2fma(a2c2, tb[4], f2mul(a1c2, f2add(nxb2, x4)));    upk(Gb[8], Gb[9], g);
            }
        }
        float asum = 0.f;
#pragma unroll
        for (int m = 0; m < M; m++) asum += fabsf(Ga[m]) + fabsf(Gb[m]);
#pragma unroll
        for (int o = 8; o; o >>= 1) asum += __shfl_xor_sync(0xffffffffu, asum, o);
        float eps = 0.05f * asum * (1.f / 170.f) + 1e-8f;
        float nie = -__fdividef(1.f, eps);
        float mx = -1e30f;
#pragma unroll
        for (int m = 0; m < M; m++) {
            Ga[m] *= nie; Gb[m] *= nie;
            if (aa) mx = fmaxf(mx, Ga[m]);
            if (ab) mx = fmaxf(mx, Gb[m]);
        }
#pragma unroll
        for (int o = 8; o; o >>= 1) mx = fmaxf(mx, __shfl_xor_sync(0xffffffffu, mx, o));
        // K rows + transposed staging store (one STS.64 per m)
        {
            float Ksa[M], Ksb[M];
#pragma unroll
            for (int m = 0; m < M; m++) {
                Ksa[m] = aa ? __expf(Ga[m] - mx) : 0.f;
                Ksb[m] = ab ? __expf(Gb[m] - mx) : 0.f;
            }
#pragma unroll
            for (int j = 0; j < 5; j++) {
                K2a[j] = pk(Ksa[2 * j], Ksa[2 * j + 1]);
                K2b[j] = pk(Ksb[2 * j], Ksb[2 * j + 1]);
            }
            if (aa) {
#pragma unroll
                for (int m = 0; m < M; m++)
                    *(u64*)&sKT[t][m][ra] = pk(Ksa[m], Ksb[m]);
            }
        }
        if (hl < RPAD) sV[t][hl] = (hl < M) ? 1.f : 0.f;
        __syncwarp();
        // Gather KT column into registers (once per outer; conflict-free 144B stride)
        if (vm) {
            ulonglong2 k01 = *(const ulonglong2*)&sKT[t][hl][0];
            ulonglong2 k23 = *(const ulonglong2*)&sKT[t][hl][4];
            ulonglong2 k45 = *(const ulonglong2*)&sKT[t][hl][8];
            ulonglong2 k67 = *(const ulonglong2*)&sKT[t][hl][12];
            KT2[0] = k01.x; KT2[1] = k01.y; KT2[2] = k23.x; KT2[3] = k23.y;
            KT2[4] = k45.x; KT2[5] = k45.y; KT2[6] = k67.x; KT2[7] = k67.y;
            kt16 = sKT[t][hl][16];
        }
        __syncwarp();

        // u-step helper (row sums against current sV)
        auto ustep = [&]() {
            ulonglong2 va = *(const ulonglong2*)&sV[t][0];
            ulonglong2 vb = *(const ulonglong2*)&sV[t][4];
            u64 vc = *(const u64*)&sV[t][8];
            u64 ca0 = f2mul(K2a[0], va.x);
            u64 ca1 = f2mul(K2a[1], va.y);
            ca0 = f2fma(K2a[2], vb.x, ca0);
            ca1 = f2fma(K2a[3], vb.y, ca1);
            ca0 = f2fma(K2a[4], vc, ca0);
            u64 acca = f2add(ca0, ca1);
            u64 cb0 = f2mul(K2b[0], va.x);
            u64 cb1 = f2mul(K2b[1], va.y);
            cb0 = f2fma(K2b[2], vb.x, cb0);
            cb1 = f2fma(K2b[3], vb.y, cb1);
            cb0 = f2fma(K2b[4], vc, cb0);
            u64 accb = f2add(cb0, cb1);
            float la, ha, lb, hb;
            upk(la, ha, acca); upk(lb, hb, accb);
            ua = __fdividef(p, fmaxf(la + ha, 1e-35f));
            ub = __fdividef(p, fmaxf(lb + hb, 1e-35f));
        };

        // Sinkhorn: u-exchange via width-16 shuffles (no smem, no extra sync);
        // v-exchange via sV + one syncwarp per iteration.
#pragma unroll 1
        for (int it = 0; it < N_SINK; it++) {
            ustep();
            u64 uab = pk(ua, ub);  // (u[2hl], u[2hl+1])
            // broadcast all u-pairs from lanes 0..8 of this half; pair j aligns with KT2[j]
            u64 up0 = shfl64h(uab, 0);
            u64 up1 = shfl64h(uab, 1);
            u64 c0 = f2mul(KT2[0], up0);
            u64 up2 = shfl64h(uab, 2);
            u64 c1 = f2mul(KT2[1], up1);
            u64 up3 = shfl64h(uab, 3);
            u64 c2 = f2mul(KT2[2], up2);
            u64 up4 = shfl64h(uab, 4);
            c0 = f2fma(KT2[3], up3, c0);
            u64 up5 = shfl64h(uab, 5);
            c1 = f2fma(KT2[4], up4, c1);
            u64 up6 = shfl64h(uab, 6);
            c2 = f2fma(KT2[5], up5, c2);
            u64 up7 = shfl64h(uab, 7);
            c0 = f2fma(KT2[6], up6, c0);
            u64 up8 = shfl64h(uab, 8);
            c1 = f2fma(KT2[7], up7, c1);
            u64 a2 = f2add(f2add(c0, c1), c2);
            float clo, chi; upk(clo, chi, a2);
            float u16lo, u16hi; upk(u16lo, u16hi, up8);   // u[16] = lo of pair 8
            float cs = (clo + chi) + kt16 * u16lo;
            if (vm)
                sV[t][hl] = __fdividef(qm, fmaxf(cs, 1e-35f));
            __syncwarp();
        }
        ustep();

        // plan = u (.) K (.) v   (reload v from sV)
        {
            ulonglong2 va = *(const ulonglong2*)&sV[t][0];
            ulonglong2 vb = *(const ulonglong2*)&sV[t][4];
            u64 vc = *(const u64*)&sV[t][8];
            if (aa) {
                u64 ua2 = pk(ua, ua);
                ulonglong2 o;
                o.x = f2mul(f2mul(ua2, K2a[0]), va.x);
                o.y = f2mul(f2mul(ua2, K2a[1]), va.y);
                *(ulonglong2*)&sP[t][ra][0] = o;
                ulonglong2 o2;
                o2.x = f2mul(f2mul(ua2, K2a[2]), vb.x);
                o2.y = f2mul(f2mul(ua2, K2a[3]), vb.y);
                *(ulonglong2*)&sP[t][ra][4] = o2;
                *(u64*)&sP[t][ra][8] = f2mul(f2mul(ua2, K2a[4]), vc);
            }
            if (ab) {
                u64 ub2 = pk(ub, ub);
                ulonglong2 o;
                o.x = f2mul(f2mul(ub2, K2b[0]), va.x);
                o.y = f2mul(f2mul(ub2, K2b[1]), va.y);
                *(ulonglong2*)&sP[t][rb][0] = o;
                ulonglong2 o2;
                o2.x = f2mul(f2mul(ub2, K2b[2]), vb.x);
                o2.y = f2mul(f2mul(ub2, K2b[3]), vb.y);
                *(ulonglong2*)&sP[t][rb][4] = o2;
                *(u64*)&sP[t][rb][8] = f2mul(f2mul(ub2, K2b[4]), vc);
            }
        }
        __syncwarp();
    }

    // final tens + contractions (v reloaded from sV; plan rows already in sP)
    u64 ta[5], tb[5];
    tens_pair(&sP[t][0][0], &sC2[t][0][0], &sC2q[t][0],
              mka, mkb, c1pa, c1pb, ta, tb);

    u64 lin2 = 0, gw2 = 0;
    {
        ulonglong2 va = *(const ulonglong2*)&sV[t][0];
        ulonglong2 vb = *(const ulonglong2*)&sV[t][4];
        u64 vc = *(const u64*)&sV[t][8];
        u64 vs[5] = { va.x, va.y, vb.x, vb.y, vc };
        if (aa) {
            u64 ua2 = pk(ua, ua);
            u64 nxa2 = pk(nxa, nxa);
            ulonglong2 x01 = __ldg((const ulonglong2*)(g_XFP + offa));
            ulonglong2 x23 = __ldg((const ulonglong2*)(g_XFP + offa + 4));
            u64 x4 = __ldg((const u64*)(g_XFP + offa + 8));
            u64 xs[5] = { x01.x, x01.y, x23.x, x23.y, x4 };
#pragma unroll
            for (int j = 0; j < 5; j++) {
                u64 pl = f2mul(f2mul(ua2, K2a[j]), vs[j]);
                lin2 = f2fma(f2add(nxa2, xs[j]), pl, lin2);
                gw2  = f2fma(ta[j], pl, gw2);
            }
        }
        if (ab) {
            u64 ub2 = pk(ub, ub);
            u64 nxb2 = pk(nxb, nxb);
            ulonglong2 x01 = __ldg((const ulonglong2*)(g_XFP + offb));
            ulonglong2 x23 = __ldg((const ulonglong2*)(g_XFP + offb + 4));
            u64 x4 = __ldg((const u64*)(g_XFP + offb + 8));
            u64 xs[5] = { x01.x, x01.y, x23.x, x23.y, x4 };
#pragma unroll
            for (int j = 0; j < 5; j++) {
                u64 pl = f2mul(f2mul(ub2, K2b[j]), vs[j]);
                lin2 = f2fma(f2add(nxb2, xs[j]), pl, lin2);
                gw2  = f2fma(tb[j], pl, gw2);
            }
        }
    }
    float llo, lhi, glo, ghi;
    upk(llo, lhi, lin2);
    upk(glo, ghi, gw2);
    float lin = llo + lhi, gw = glo + ghi;
#pragma unroll
    for (int o = 8; o; o >>= 1) {
        lin += __shfl_xor_sync(0xffffffffu, lin, o);
        gw  += __shfl_xor_sync(0xffffffffu, gw, o);
    }
    if (hl == 0)
        out[n * T + t] = a1c * lin + alpha * gw;
}

extern "C" void kernel_launch(void* const* d_in, const int* in_sizes, int n_in,
                              void* d_out, int out_size)
{
    const float* x      = (const float*)d_in[0];
    const int*   ei     = (const int*)d_in[1];
    const float* C2g    = (const float*)d_in[2];
    const float* F2g    = (const float*)d_in[3];
    const float* q0     = (const float*)d_in[4];
    const float* alpha0 = (const float*)d_in[5];
    float* out = (float*)d_out;

    const int* edge_dst = ei + NNODES * DEG;

    xf2_kernel<<<NNODES / 4, 128>>>(x, F2g);
    ltfgw_kernel<<<NNODES, 160>>>(edge_dst, C2g, q0, alpha0, out);
}

// round 16
// speedup vs baseline: 1.0206x; 1.0206x over previous
#include <cuda_runtime.h>

#define NNODES 20000
#define DEG 16
#define S 17
#define T 10
#define M 10
#define D 128
#define N_OUTER 5
#define N_SINK 15
#define RPAD 12     // 10 padded to 12 (48B rows, 16B-aligned)
#define UPAD 20     // u rows: 18 padded to 20 (80B, 16B-aligned)
#define KTPAD 36    // KT staging rows: 144B stride -> conflict-free LDS.128 gather

typedef unsigned long long u64;

// ---- packed f32x2 helpers (sm_100+) ----
__device__ __forceinline__ u64 pk(float lo, float hi) {
    u64 r; asm("mov.b64 %0,{%1,%2};" : "=l"(r) : "f"(lo), "f"(hi)); return r;
}
__device__ __forceinline__ void upk(float& lo, float& hi, u64 v) {
    asm("mov.b64 {%0,%1},%2;" : "=f"(lo), "=f"(hi) : "l"(v));
}
__device__ __forceinline__ u64 f2fma(u64 a, u64 b, u64 c) {
    u64 d; asm("fma.rn.f32x2 %0,%1,%2,%3;" : "=l"(d) : "l"(a), "l"(b), "l"(c)); return d;
}
__device__ __forceinline__ u64 f2mul(u64 a, u64 b) {
    u64 d; asm("mul.rn.f32x2 %0,%1,%2;" : "=l"(d) : "l"(a), "l"(b)); return d;
}
__device__ __forceinline__ u64 f2add(u64 a, u64 b) {
    u64 d; asm("add.rn.f32x2 %0,%1,%2;" : "=l"(d) : "l"(a), "l"(b)); return d;
}

// Precomputed: XFP[n][t][m] = ||F2[t][m]||^2 - 2 x[n].F2[t][m],  NX[n] = ||x[n]||^2
__device__ float g_XFP[(long)NNODES * T * RPAD];
__device__ float g_NX[NNODES];

__global__ __launch_bounds__(128)
void xf2_kernel(const float* __restrict__ x, const float* __restrict__ F2g)
{
    __shared__ float sx[4][D];
    const int tid = threadIdx.x;
    const int nbase = blockIdx.x * 4;
#pragma unroll
    for (int i = 0; i < 4; i++)
        sx[i][tid] = x[(long)(nbase + i) * D + tid];
    __syncthreads();

    if (tid < T * M) {
        const float* f2 = F2g + tid * D;
        float a0 = 0.f, a1 = 0.f, a2 = 0.f, a3 = 0.f, nf = 0.f;
#pragma unroll 8
        for (int c = 0; c < D / 4; c++) {
            float4 f = __ldg((const float4*)(f2 + 4 * c));
            nf = fmaf(f.x, f.x, fmaf(f.y, f.y, fmaf(f.z, f.z, fmaf(f.w, f.w, nf))));
            float4 x0 = *(const float4*)&sx[0][4 * c];
            a0 = fmaf(f.x, x0.x, fmaf(f.y, x0.y, fmaf(f.z, x0.z, fmaf(f.w, x0.w, a0))));
            float4 x1 = *(const float4*)&sx[1][4 * c];
            a1 = fmaf(f.x, x1.x, fmaf(f.y, x1.y, fmaf(f.z, x1.z, fmaf(f.w, x1.w, a1))));
            float4 x2 = *(const float4*)&sx[2][4 * c];
            a2 = fmaf(f.x, x2.x, fmaf(f.y, x2.y, fmaf(f.z, x2.z, fmaf(f.w, x2.w, a2))));
            float4 x3 = *(const float4*)&sx[3][4 * c];
            a3 = fmaf(f.x, x3.x, fmaf(f.y, x3.y, fmaf(f.z, x3.z, fmaf(f.w, x3.w, a3))));
        }
        const int t = tid / M, m = tid % M;
        g_XFP[((long)(nbase + 0) * T + t) * RPAD + m] = nf - 2.f * a0;
        g_XFP[((long)(nbase + 1) * T + t) * RPAD + m] = nf - 2.f * a1;
        g_XFP[((long)(nbase + 2) * T + t) * RPAD + m] = nf - 2.f * a2;
        g_XFP[((long)(nbase + 3) * T + t) * RPAD + m] = nf - 2.f * a3;
    } else if (tid < T * M + 4) {
        const int nn = tid - T * M;
        float a = 0.f;
#pragma unroll 8
        for (int c = 0; c < D / 4; c++) {
            float4 v = *(const float4*)&sx[nn][4 * c];
            a = fmaf(v.x, v.x, fmaf(v.y, v.y, fmaf(v.z, v.z, fmaf(v.w, v.w, a))));
        }
        g_NX[nbase + nn] = a;
    }
}

// Fused tens for TWO rows of the same template. C2w holds (-2*C2).
__device__ __forceinline__ void tens_pair(const float* Pw, const float* C2w,
                                          const float* c2qw,
                                          unsigned mka, unsigned mkb,
                                          float c1pa, float c1pb,
                                          u64* ta, u64* tb)
{
    u64 Aa0 = 0, Aa1 = 0, Aa2 = 0, Aa3 = 0, Aa4 = 0;
    u64 Ab0 = 0, Ab1 = 0, Ab2 = 0, Ab3 = 0, Ab4 = 0;
#pragma unroll
    for (int uu = 0; uu < S; uu++) {
        const float* pr = Pw + uu * RPAD;
        ulonglong2 r01 = *(const ulonglong2*)pr;
        ulonglong2 r23 = *(const ulonglong2*)(pr + 4);
        u64 r4 = *(const u64*)(pr + 8);
        unsigned ba = (mka >> uu) & 1u;
        unsigned bb = (mkb >> uu) & 1u;
        asm("{\n\t.reg .pred pa,pb;\n\t"
            "setp.ne.u32 pa,%10,0;\n\t"
            "setp.ne.u32 pb,%11,0;\n\t"
            "@pa add.rn.f32x2 %0,%0,%12;\n\t"
            "@pa add.rn.f32x2 %1,%1,%13;\n\t"
            "@pa add.rn.f32x2 %2,%2,%14;\n\t"
            "@pa add.rn.f32x2 %3,%3,%15;\n\t"
            "@pa add.rn.f32x2 %4,%4,%16;\n\t"
            "@pb add.rn.f32x2 %5,%5,%12;\n\t"
            "@pb add.rn.f32x2 %6,%6,%13;\n\t"
            "@pb add.rn.f32x2 %7,%7,%14;\n\t"
            "@pb add.rn.f32x2 %8,%8,%15;\n\t"
            "@pb add.rn.f32x2 %9,%9,%16;\n\t}"
            : "+l"(Aa0), "+l"(Aa1), "+l"(Aa2), "+l"(Aa3), "+l"(Aa4),
              "+l"(Ab0), "+l"(Ab1), "+l"(Ab2), "+l"(Ab3), "+l"(Ab4)
            : "r"(ba), "r"(bb),
              "l"(r01.x), "l"(r01.y), "l"(r23.x), "l"(r23.y), "l"(r4));
    }
    {
        u64 ca2 = pk(c1pa, c1pa);
        u64 cb2 = pk(c1pb, c1pb);
        ulonglong2 cq01 = *(const ulonglong2*)c2qw;
        ulonglong2 cq23 = *(const ulonglong2*)(c2qw + 4);
        u64 cq4 = *(const u64*)(c2qw + 8);
        ta[0] = f2add(ca2, cq01.x); tb[0] = f2add(cb2, cq01.x);
        ta[1] = f2add(ca2, cq01.y); tb[1] = f2add(cb2, cq01.y);
        ta[2] = f2add(ca2, cq23.x); tb[2] = f2add(cb2, cq23.x);
        ta[3] = f2add(ca2, cq23.y); tb[3] = f2add(cb2, cq23.y);
        ta[4] = f2add(ca2, cq4);    tb[4] = f2add(cb2, cq4);
    }
    float aav[M], abv[M];
    upk(aav[0], aav[1], Aa0); upk(aav[2], aav[3], Aa1); upk(aav[4], aav[5], Aa2);
    upk(aav[6], aav[7], Aa3); upk(aav[8], aav[9], Aa4);
    upk(abv[0], abv[1], Ab0); upk(abv[2], abv[3], Ab1); upk(abv[4], abv[5], Ab2);
    upk(abv[6], abv[7], Ab3); upk(abv[8], abv[9], Ab4);
#pragma unroll
    for (int v = 0; v < M; v++) {
        u64 ava2 = pk(aav[v], aav[v]);
        u64 avb2 = pk(abv[v], abv[v]);
        const float* c2r = C2w + v * RPAD;
        ulonglong2 c01 = *(const ulonglong2*)c2r;
        ulonglong2 c23 = *(const ulonglong2*)(c2r + 4);
        u64 c4 = *(const u64*)(c2r + 8);
        ta[0] = f2fma(ava2, c01.x, ta[0]); tb[0] = f2fma(avb2, c01.x, tb[0]);
        ta[1] = f2fma(ava2, c01.y, ta[1]); tb[1] = f2fma(avb2, c01.y, tb[1]);
        ta[2] = f2fma(ava2, c23.x, ta[2]); tb[2] = f2fma(avb2, c23.x, tb[2]);
        ta[3] = f2fma(ava2, c23.y, ta[3]); tb[3] = f2fma(avb2, c23.y, tb[3]);
        ta[4] = f2fma(ava2, c4,    ta[4]); tb[4] = f2fma(avb2, c4,    tb[4]);
    }
}

// 160 threads = 5 warps; warp ww serves templates 2ww (lanes 0-15) and 2ww+1 (lanes 16-31).
// Each lane owns rows ra=2*hl, rb=2*hl+1 (hl = lane % 16).
__global__ __launch_bounds__(160, 5)
void ltfgw_kernel(const int* __restrict__ edge_dst,
                  const float* __restrict__ C2g,
                  const float* __restrict__ q0,
                  const float* __restrict__ alpha0,
                  float* __restrict__ out)
{
    __shared__ __align__(16) int      sNodes[S];
    __shared__ __align__(16) unsigned sMask[S];
    __shared__ __align__(16) float    sQ[RPAD];
    __shared__ __align__(16) float    sC2[T][M][RPAD];    // holds -2*C2
    __shared__ __align__(16) float    sC2q[T][RPAD];
    __shared__ __align__(16) float    sOPC[T][RPAD];      // 1 + sum_b q[b]*(-2 C2[b][m])
    __shared__ __align__(16) float    sP[T][S][RPAD];
    __shared__ __align__(16) float    sKT[T][M][KTPAD];   // transposed K staging (per outer)
    __shared__ __align__(16) float    sV[T][RPAD];
    __shared__ __align__(16) float    sU[T][UPAD];

    const int n    = blockIdx.x;
    const int tid  = threadIdx.x;
    const int ww   = tid >> 5;
    const int lane = tid & 31;
    const int half = lane >> 4;
    const int hl   = lane & 15;
    const int t    = 2 * ww + half;
    const int ra   = 2 * hl;
    const int rb   = ra + 1;
    const bool aa  = (ra < S);   // hl <= 8
    const bool ab  = (rb < S);   // hl <= 7
    const bool vm  = (hl < M);

    if (tid < S) sNodes[tid] = (tid == 0) ? n : edge_dst[n * DEG + tid - 1];
    if (tid == 0) {
        float qq[M];
        float mxq = -1e30f;
#pragma unroll
        for (int m = 0; m < M; m++) { qq[m] = q0[m]; mxq = fmaxf(mxq, qq[m]); }
        float ssum = 0.f;
#pragma unroll
        for (int m = 0; m < M; m++) { qq[m] = __expf(qq[m] - mxq); ssum += qq[m]; }
        float inv = 1.f / ssum;
#pragma unroll
        for (int m = 0; m < M; m++) sQ[m] = qq[m] * inv;
        sQ[10] = 0.f; sQ[11] = 0.f;
    }
    __syncthreads();

    // C1 bitmask (warp 0)
    if (ww == 0) {
        int nodesr[S];
#pragma unroll
        for (int i = 0; i < S; i++) nodesr[i] = sNodes[i];
        unsigned msk0 = 0;
        if (lane < S) {
            int me = nodesr[lane];
#pragma unroll
            for (int kk = 0; kk < DEG / 4; kk++) {
                int4 nb4 = *(const int4*)(edge_dst + me * DEG + kk * 4);
                int nbs[4] = { nb4.x, nb4.y, nb4.z, nb4.w };
#pragma unroll
                for (int j = 0; j < 4; j++) {
#pragma unroll
                    for (int s2 = 0; s2 < S; s2++)
                        if (nbs[j] == nodesr[s2]) msk0 |= 1u << s2;
                }
            }
        }
        unsigned add = 0;
#pragma unroll
        for (int s2 = 0; s2 < S; s2++) {
            unsigned col = __ballot_sync(0xffffffffu, (msk0 >> s2) & 1u);
            if (lane == s2) add = col;
        }
        msk0 |= add & 0x1FFFFu;
        if (lane < S) sMask[lane] = msk0;
    }

    // C2 staging: store -2*C2; compute sC2q and sOPC
    if (vm) {
        float acc = 0.f;   // sum_b C2[m][b]^2 q[b]   (row m = hl)
        float acc2 = 0.f;  // sum_b q[b] * (-2 C2[b][hl])  (column hl)
#pragma unroll
        for (int r = 0; r < M; r++) {
            float c = __ldg(C2g + (t * M + r) * M + hl);   // C2[r][hl]
            sC2[t][r][hl] = -2.f * c;
            acc2 = fmaf(sQ[r], -2.f * c, acc2);
        }
#pragma unroll
        for (int b = 0; b < M; b++) {
            float c = __ldg(C2g + (t * M + hl) * M + b);   // C2[hl][b]
            acc = fmaf(c * c, sQ[b], acc);
        }
        sC2q[t][hl] = acc;
        sOPC[t][hl] = 1.f + acc2;
    }
    if (hl >= M && hl < RPAD) { sC2q[t][hl] = 0.f; sOPC[t][hl] = 0.f; }

    // BARRIER before any thread reads sMask (written by warp 0 only).
    __syncthreads();

    const int nodea = aa ? sNodes[ra] : 0;
    const int nodeb = ab ? sNodes[rb] : 0;
    const int offa = (nodea * T + t) * RPAD;
    const int offb = (nodeb * T + t) * RPAD;
    const float nxa = aa ? __ldg(g_NX + nodea) : 0.f;
    const float nxb = ab ? __ldg(g_NX + nodeb) : 0.f;

    const float alpha = 1.f / (1.f + __expf(-__ldg(alpha0 + n)));
    const float a1c = 1.f - alpha;
    const float a2c = 2.f * alpha;
    const float p = 1.f / 17.f;
    const unsigned mka = aa ? sMask[ra] : 0u;
    const unsigned mkb = ab ? sMask[rb] : 0u;
    const float c1pa = (float)__popc(mka) * (1.f / 17.f);
    const float c1pb = (float)__popc(mkb) * (1.f / 17.f);
    const float qm = vm ? sQ[hl] : 0.f;

    u64 K2a[5], K2b[5];
    u64 KT2[8]; float kt16 = 0.f;
#pragma unroll
    for (int j = 0; j < 8; j++) KT2[j] = 0;
    float ua = 0.f, ub = 0.f;

#pragma unroll 1
    for (int outer = 0; outer < N_OUTER; outer++) {
        u64 ta[5], tb[5];
        if (outer == 0) {
            // closed form from plan0 = p (x) q:
            // tens0[r][m] = c1p_r * (1 + cq2[m]) + c2q[m] = c1p_r * OPC[m] + C2q[m]
            u64 ca2 = pk(c1pa, c1pa);
            u64 cb2 = pk(c1pb, c1pb);
            ulonglong2 op01 = *(const ulonglong2*)&sOPC[t][0];
            ulonglong2 op23 = *(const ulonglong2*)&sOPC[t][4];
            u64 op4 = *(const u64*)&sOPC[t][8];
            ulonglong2 cq01 = *(const ulonglong2*)&sC2q[t][0];
            ulonglong2 cq23 = *(const ulonglong2*)&sC2q[t][4];
            u64 cq4 = *(const u64*)&sC2q[t][8];
            ta[0] = f2fma(ca2, op01.x, cq01.x); tb[0] = f2fma(cb2, op01.x, cq01.x);
            ta[1] = f2fma(ca2, op01.y, cq01.y); tb[1] = f2fma(cb2, op01.y, cq01.y);
            ta[2] = f2fma(ca2, op23.x, cq23.x); tb[2] = f2fma(cb2, op23.x, cq23.x);
            ta[3] = f2fma(ca2, op23.y, cq23.y); tb[3] = f2fma(cb2, op23.y, cq23.y);
            ta[4] = f2fma(ca2, op4,    cq4);    tb[4] = f2fma(cb2, op4,    cq4);
        } else {
            tens_pair(&sP[t][0][0], &sC2[t][0][0], &sC2q[t][0],
                      mka, mkb, c1pa, c1pb, ta, tb);
        }

        // G rows, eps from |G| mean over template, K = exp(-G/eps - mx)
        float Ga[M], Gb[M];
#pragma unroll
        for (int m = 0; m < M; m++) { Ga[m] = 0.f; Gb[m] = 0.f; }
        {
            u64 a1c2 = pk(a1c, a1c);
            u64 a2c2 = pk(a2c, a2c);
            if (aa) {
                u64 nxa2 = pk(nxa, nxa);
                ulonglong2 x01 = __ldg((const ulonglong2*)(g_XFP + offa));
                ulonglong2 x23 = __ldg((const ulonglong2*)(g_XFP + offa + 4));
                u64 x4 = __ldg((const u64*)(g_XFP + offa + 8));
                u64 g;
                g = f2fma(a2c2, ta[0], f2mul(a1c2, f2add(nxa2, x01.x))); upk(Ga[0], Ga[1], g);
                g = f2fma(a2c2, ta[1], f2mul(a1c2, f2add(nxa2, x01.y))); upk(Ga[2], Ga[3], g);
                g = f2fma(a2c2, ta[2], f2mul(a1c2, f2add(nxa2, x23.x))); upk(Ga[4], Ga[5], g);
                g = f2fma(a2c2, ta[3], f2mul(a1c2, f2add(nxa2, x23.y))); upk(Ga[6], Ga[7], g);
                g = f2fma(a2c2, ta[4], f2mul(a1c2, f2add(nxa2, x4)));    upk(Ga[8], Ga[9], g);
            }
            if (ab) {
                u64 nxb2 = pk(nxb, nxb);
                ulonglong2 x01 = __ldg((const ulonglong2*)(g_XFP + offb));
                ulonglong2 x23 = __ldg((const ulonglong2*)(g_XFP + offb + 4));
                u64 x4 = __ldg((const u64*)(g_XFP + offb + 8));
                u64 g;
                g = f2fma(a2c2, tb[0], f2mul(a1c2, f2add(nxb2, x01.x))); upk(Gb[0], Gb[1], g);
                g = f2fma(a2c2, tb[1], f2mul(a1c2, f2add(nxb2, x01.y))); upk(Gb[2], Gb[3], g);
                g = f2fma(a2c2, tb[2], f2mul(a1c2, f2add(nxb2, x23.x))); upk(Gb[4], Gb[5], g);
                g = f2fma(a2c2, tb[3], f2mul(a1c2, f2add(nxb2, x23.y))); upk(Gb[6], Gb[7], g);
                g = f2fma(a2c2, tb[4], f2mul(a1c2, f2add(nxb2, x4)));    upk(Gb[8], Gb[9], g);
            }
        }
        float asum = 0.f;
#pragma unroll
        for (int m = 0; m < M; m++) asum += fabsf(Ga[m]) + fabsf(Gb[m]);
#pragma unroll
        for (int o = 8; o; o >>= 1) asum += __shfl_xor_sync(0xffffffffu, asum, o);
        float eps = 0.05f * asum * (1.f / 170.f) + 1e-8f;
        float nie = -__fdividef(1.f, eps);
        float mx = -1e30f;
#pragma unroll
        for (int m = 0; m < M; m++) {
            Ga[m] *= nie; Gb[m] *= nie;
            if (aa) mx = fmaxf(mx, Ga[m]);
            if (ab) mx = fmaxf(mx, Gb[m]);
        }
#pragma unroll
        for (int o = 8; o; o >>= 1) mx = fmaxf(mx, __shfl_xor_sync(0xffffffffu, mx, o));
        // K rows + transposed staging store (one STS.64 per m)
        {
            float Ksa[M], Ksb[M];
#pragma unroll
            for (int m = 0; m < M; m++) {
                Ksa[m] = aa ? __expf(Ga[m] - mx) : 0.f;
                Ksb[m] = ab ? __expf(Gb[m] - mx) : 0.f;
            }
#pragma unroll
            for (int j = 0; j < 5; j++) {
                K2a[j] = pk(Ksa[2 * j], Ksa[2 * j + 1]);
                K2b[j] = pk(Ksb[2 * j], Ksb[2 * j + 1]);
            }
            if (aa) {
#pragma unroll
                for (int m = 0; m < M; m++)
                    *(u64*)&sKT[t][m][ra] = pk(Ksa[m], Ksb[m]);
            }
        }
        if (hl < RPAD) sV[t][hl] = (hl < M) ? 1.f : 0.f;
        __syncwarp();
        // Gather KT column into registers (once per outer; conflict-free 144B stride)
        if (vm) {
            ulonglong2 k01 = *(const ulonglong2*)&sKT[t][hl][0];
            ulonglong2 k23 = *(const ulonglong2*)&sKT[t][hl][4];
            ulonglong2 k45 = *(const ulonglong2*)&sKT[t][hl][8];
            ulonglong2 k67 = *(const ulonglong2*)&sKT[t][hl][12];
            KT2[0] = k01.x; KT2[1] = k01.y; KT2[2] = k23.x; KT2[3] = k23.y;
            KT2[4] = k45.x; KT2[5] = k45.y; KT2[6] = k67.x; KT2[7] = k67.y;
            kt16 = sKT[t][hl][16];
        }
        __syncwarp();

        // u-step helper (row sums against current sV)
        auto ustep = [&]() {
            ulonglong2 va = *(const ulonglong2*)&sV[t][0];
            ulonglong2 vb = *(const ulonglong2*)&sV[t][4];
            u64 vc = *(const u64*)&sV[t][8];
            u64 ca0 = f2mul(K2a[0], va.x);
            u64 ca1 = f2mul(K2a[1], va.y);
            ca0 = f2fma(K2a[2], vb.x, ca0);
            ca1 = f2fma(K2a[3], vb.y, ca1);
            ca0 = f2fma(K2a[4], vc, ca0);
            u64 acca = f2add(ca0, ca1);
            u64 cb0 = f2mul(K2b[0], va.x);
            u64 cb1 = f2mul(K2b[1], va.y);
            cb0 = f2fma(K2b[2], vb.x, cb0);
            cb1 = f2fma(K2b[3], vb.y, cb1);
            cb0 = f2fma(K2b[4], vc, cb0);
            u64 accb = f2add(cb0, cb1);
            float la, ha, lb, hb;
            upk(la, ha, acca); upk(lb, hb, accb);
            ua = __fdividef(p, fmaxf(la + ha, 1e-35f));
            ub = __fdividef(p, fmaxf(lb + hb, 1e-35f));
        };

        // Sinkhorn: runtime loop (15 u,v iterations) + peeled final u-step
#pragma unroll 1
        for (int it = 0; it < N_SINK; it++) {
            ustep();
            if (hl < 9) *(u64*)&sU[t][ra] = pk(ua, ub);
            __syncwarp();
            if (vm) {
                ulonglong2 u01 = *(const ulonglong2*)&sU[t][0];
                ulonglong2 u23 = *(const ulonglong2*)&sU[t][4];
                ulonglong2 u45 = *(const ulonglong2*)&sU[t][8];
                ulonglong2 u67 = *(const ulonglong2*)&sU[t][12];
                float u16 = sU[t][16];
                u64 c0 = f2mul(KT2[0], u01.x);
                u64 c1 = f2mul(KT2[1], u01.y);
                u64 c2 = f2mul(KT2[2], u23.x);
                c0 = f2fma(KT2[3], u23.y, c0);
                c1 = f2fma(KT2[4], u45.x, c1);
                c2 = f2fma(KT2[5], u45.y, c2);
                c0 = f2fma(KT2[6], u67.x, c0);
                c1 = f2fma(KT2[7], u67.y, c1);
                u64 a2 = f2add(f2add(c0, c1), c2);
                float clo, chi; upk(clo, chi, a2);
                float cs = (clo + chi) + kt16 * u16;
                sV[t][hl] = __fdividef(qm, fmaxf(cs, 1e-35f));
            }
            __syncwarp();
        }
        ustep();

        // plan = u (.) K (.) v   (reload v from sV)
        {
            ulonglong2 va = *(const ulonglong2*)&sV[t][0];
            ulonglong2 vb = *(const ulonglong2*)&sV[t][4];
            u64 vc = *(const u64*)&sV[t][8];
            if (aa) {
                u64 ua2 = pk(ua, ua);
                ulonglong2 o;
                o.x = f2mul(f2mul(ua2, K2a[0]), va.x);
                o.y = f2mul(f2mul(ua2, K2a[1]), va.y);
                *(ulonglong2*)&sP[t][ra][0] = o;
                ulonglong2 o2;
                o2.x = f2mul(f2mul(ua2, K2a[2]), vb.x);
                o2.y = f2mul(f2mul(ua2, K2a[3]), vb.y);
                *(ulonglong2*)&sP[t][ra][4] = o2;
                *(u64*)&sP[t][ra][8] = f2mul(f2mul(ua2, K2a[4]), vc);
            }
            if (ab) {
                u64 ub2 = pk(ub, ub);
                ulonglong2 o;
                o.x = f2mul(f2mul(ub2, K2b[0]), va.x);
                o.y = f2mul(f2mul(ub2, K2b[1]), va.y);
                *(ulonglong2*)&sP[t][rb][0] = o;
                ulonglong2 o2;
                o2.x = f2mul(f2mul(ub2, K2b[2]), vb.x);
                o2.y = f2mul(f2mul(ub2, K2b[3]), vb.y);
                *(ulonglong2*)&sP[t][rb][4] = o2;
                *(u64*)&sP[t][rb][8] = f2mul(f2mul(ub2, K2b[4]), vc);
            }
        }
        __syncwarp();
    }

    // final tens + contractions (v reloaded from sV; plan rows already in sP)
    u64 ta[5], tb[5];
    tens_pair(&sP[t][0][0], &sC2[t][0][0], &sC2q[t][0],
              mka, mkb, c1pa, c1pb, ta, tb);

    u64 lin2 = 0, gw2 = 0;
    {
        ulonglong2 va = *(const ulonglong2*)&sV[t][0];
        ulonglong2 vb = *(const ulonglong2*)&sV[t][4];
        u64 vc = *(const u64*)&sV[t][8];
        u64 vs[5] = { va.x, va.y, vb.x, vb.y, vc };
        if (aa) {
            u64 ua2 = pk(ua, ua);
            u64 nxa2 = pk(nxa, nxa);
            ulonglong2 x01 = __ldg((const ulonglong2*)(g_XFP + offa));
            ulonglong2 x23 = __ldg((const ulonglong2*)(g_XFP + offa + 4));
            u64 x4 = __ldg((const u64*)(g_XFP + offa + 8));
            u64 xs[5] = { x01.x, x01.y, x23.x, x23.y, x4 };
#pragma unroll
            for (int j = 0; j < 5; j++) {
                u64 pl = f2mul(f2mul(ua2, K2a[j]), vs[j]);
                lin2 = f2fma(f2add(nxa2, xs[j]), pl, lin2);
                gw2  = f2fma(ta[j], pl, gw2);
            }
        }
        if (ab) {
            u64 ub2 = pk(ub, ub);
            u64 nxb2 = pk(nxb, nxb);
            ulonglong2 x01 = __ldg((const ulonglong2*)(g_XFP + offb));
            ulonglong2 x23 = __ldg((const ulonglong2*)(g_XFP + offb + 4));
            u64 x4 = __ldg((const u64*)(g_XFP + offb + 8));
            u64 xs[5] = { x01.x, x01.y, x23.x, x23.y, x4 };
#pragma unroll
            for (int j = 0; j < 5; j++) {
                u64 pl = f2mul(f2mul(ub2, K2b[j]), vs[j]);
                lin2 = f2fma(f2add(nxb2, xs[j]), pl, lin2);
                gw2  = f2fma(tb[j], pl, gw2);
            }
        }
    }
    float llo, lhi, glo, ghi;
    upk(llo, lhi, lin2);
    upk(glo, ghi, gw2);
    float lin = llo + lhi, gw = glo + ghi;
#pragma unroll
    for (int o = 8; o; o >>= 1) {
        lin += __shfl_xor_sync(0xffffffffu, lin, o);
        gw  += __shfl_xor_sync(0xffffffffu, gw, o);
    }
    if (hl == 0)
        out[n * T + t] = a1c * lin + alpha * gw;
}

extern "C" void kernel_launch(void* const* d_in, const int* in_sizes, int n_in,
                              void* d_out, int out_size)
{
    const float* x      = (const float*)d_in[0];
    const int*   ei     = (const int*)d_in[1];
    const float* C2g    = (const float*)d_in[2];
    const float* F2g    = (const float*)d_in[3];
    const float* q0     = (const float*)d_in[4];
    const float* alpha0 = (const float*)d_in[5];
    float* out = (float*)d_out;

    const int* edge_dst = ei + NNODES * DEG;

    xf2_kernel<<<NNODES / 4, 128>>>(x, F2g);
    ltfgw_kernel<<<NNODES, 160>>>(edge_dst, C2g, q0, alpha0, out);
}

// round 17
// speedup vs baseline: 1.0496x; 1.0285x over previous
#include <cuda_runtime.h>

#define NNODES 20000
#define DEG 16
#define S 17
#define T 10
#define M 10
#define D 128
#define N_OUTER 5
#define N_SINK 15
#define RPAD 12     // 10 padded to 12 (48B rows, 16B-aligned)
#define UPAD 20     // u rows: 18 padded to 20 (80B, 16B-aligned)
#define KTPAD 36    // KT staging rows: 144B stride -> conflict-free LDS.128 gather
#define MPAD 18     // mask row pad: 72B rows -> 8B-aligned u64 loads

typedef unsigned long long u64;

// ---- packed f32x2 helpers (sm_100+) ----
__device__ __forceinline__ u64 pk(float lo, float hi) {
    u64 r; asm("mov.b64 %0,{%1,%2};" : "=l"(r) : "f"(lo), "f"(hi)); return r;
}
__device__ __forceinline__ void upk(float& lo, float& hi, u64 v) {
    asm("mov.b64 {%0,%1},%2;" : "=f"(lo), "=f"(hi) : "l"(v));
}
__device__ __forceinline__ u64 f2fma(u64 a, u64 b, u64 c) {
    u64 d; asm("fma.rn.f32x2 %0,%1,%2,%3;" : "=l"(d) : "l"(a), "l"(b), "l"(c)); return d;
}
__device__ __forceinline__ u64 f2mul(u64 a, u64 b) {
    u64 d; asm("mul.rn.f32x2 %0,%1,%2;" : "=l"(d) : "l"(a), "l"(b)); return d;
}
__device__ __forceinline__ u64 f2add(u64 a, u64 b) {
    u64 d; asm("add.rn.f32x2 %0,%1,%2;" : "=l"(d) : "l"(a), "l"(b)); return d;
}

// Precomputed: XFP[n][t][m] = ||F2[t][m]||^2 - 2 x[n].F2[t][m],  NX[n] = ||x[n]||^2
__device__ float    g_XFP[(long)NNODES * T * RPAD];
__device__ float    g_NX[NNODES];
__device__ float    g_Q[RPAD];
__device__ unsigned g_MaskP[(long)NNODES * MPAD];

__global__ __launch_bounds__(128)
void xf2_kernel(const float* __restrict__ x, const float* __restrict__ F2g,
                const float* __restrict__ q0)
{
    __shared__ float sx[4][D];
    const int tid = threadIdx.x;
    const int nbase = blockIdx.x * 4;
#pragma unroll
    for (int i = 0; i < 4; i++)
        sx[i][tid] = x[(long)(nbase + i) * D + tid];
    __syncthreads();

    if (tid < T * M) {
        const float* f2 = F2g + tid * D;
        float a0 = 0.f, a1 = 0.f, a2 = 0.f, a3 = 0.f, nf = 0.f;
#pragma unroll 8
        for (int c = 0; c < D / 4; c++) {
            float4 f = __ldg((const float4*)(f2 + 4 * c));
            nf = fmaf(f.x, f.x, fmaf(f.y, f.y, fmaf(f.z, f.z, fmaf(f.w, f.w, nf))));
            float4 x0 = *(const float4*)&sx[0][4 * c];
            a0 = fmaf(f.x, x0.x, fmaf(f.y, x0.y, fmaf(f.z, x0.z, fmaf(f.w, x0.w, a0))));
            float4 x1 = *(const float4*)&sx[1][4 * c];
            a1 = fmaf(f.x, x1.x, fmaf(f.y, x1.y, fmaf(f.z, x1.z, fmaf(f.w, x1.w, a1))));
            float4 x2 = *(const float4*)&sx[2][4 * c];
            a2 = fmaf(f.x, x2.x, fmaf(f.y, x2.y, fmaf(f.z, x2.z, fmaf(f.w, x2.w, a2))));
            float4 x3 = *(const float4*)&sx[3][4 * c];
            a3 = fmaf(f.x, x3.x, fmaf(f.y, x3.y, fmaf(f.z, x3.z, fmaf(f.w, x3.w, a3))));
        }
        const int t = tid / M, m = tid % M;
        g_XFP[((long)(nbase + 0) * T + t) * RPAD + m] = nf - 2.f * a0;
        g_XFP[((long)(nbase + 1) * T + t) * RPAD + m] = nf - 2.f * a1;
        g_XFP[((long)(nbase + 2) * T + t) * RPAD + m] = nf - 2.f * a2;
        g_XFP[((long)(nbase + 3) * T + t) * RPAD + m] = nf - 2.f * a3;
    } else if (tid < T * M + 4) {
        const int nn = tid - T * M;
        float a = 0.f;
#pragma unroll 8
        for (int c = 0; c < D / 4; c++) {
            float4 v = *(const float4*)&sx[nn][4 * c];
            a = fmaf(v.x, v.x, fmaf(v.y, v.y, fmaf(v.z, v.z, fmaf(v.w, v.w, a))));
        }
        g_NX[nbase + nn] = a;
    } else if (blockIdx.x == 0 && tid == 127) {
        // q softmax (once globally)
        float qq[M];
        float mxq = -1e30f;
#pragma unroll
        for (int m = 0; m < M; m++) { qq[m] = q0[m]; mxq = fmaxf(mxq, qq[m]); }
        float ssum = 0.f;
#pragma unroll
        for (int m = 0; m < M; m++) { qq[m] = __expf(qq[m] - mxq); ssum += qq[m]; }
        float inv = 1.f / ssum;
#pragma unroll
        for (int m = 0; m < M; m++) g_Q[m] = qq[m] * inv;
        g_Q[10] = 0.f; g_Q[11] = 0.f;
    }
}

// One warp per node: build symmetrized C1 bitmasks into g_MaskP[n][0..16] (slot 17 = 0).
__global__ __launch_bounds__(256)
void mask_kernel(const int* __restrict__ edge_dst)
{
    const int wid_g = (blockIdx.x * blockDim.x + threadIdx.x) >> 5;
    const int lane = threadIdx.x & 31;
    if (wid_g >= NNODES) return;
    const int n = wid_g;
    int my = 0;
    if (lane < S) my = (lane == 0) ? n : edge_dst[n * DEG + lane - 1];
    int nodesr[S];
#pragma unroll
    for (int i = 0; i < S; i++) nodesr[i] = __shfl_sync(0xffffffffu, my, i);
    unsigned msk0 = 0;
    if (lane < S) {
        int me = nodesr[lane];
#pragma unroll
        for (int kk = 0; kk < DEG / 4; kk++) {
            int4 nb4 = *(const int4*)(edge_dst + me * DEG + kk * 4);
            int nbs[4] = { nb4.x, nb4.y, nb4.z, nb4.w };
#pragma unroll
            for (int j = 0; j < 4; j++) {
#pragma unroll
                for (int s2 = 0; s2 < S; s2++)
                    if (nbs[j] == nodesr[s2]) msk0 |= 1u << s2;
            }
        }
    }
    unsigned add = 0;
#pragma unroll
    for (int s2 = 0; s2 < S; s2++) {
        unsigned col = __ballot_sync(0xffffffffu, (msk0 >> s2) & 1u);
        if (lane == s2) add = col;
    }
    msk0 |= add & 0x1FFFFu;
    if (lane < S) g_MaskP[(long)n * MPAD + lane] = msk0;
    if (lane == S) g_MaskP[(long)n * MPAD + S] = 0u;
}

// Fused tens for TWO rows of the same template. C2w holds (-2*C2).
__device__ __forceinline__ void tens_pair(const float* Pw, const float* C2w,
                                          const float* c2qw,
                                          unsigned mka, unsigned mkb,
                                          float c1pa, float c1pb,
                                          u64* ta, u64* tb)
{
    u64 Aa0 = 0, Aa1 = 0, Aa2 = 0, Aa3 = 0, Aa4 = 0;
    u64 Ab0 = 0, Ab1 = 0, Ab2 = 0, Ab3 = 0, Ab4 = 0;
#pragma unroll
    for (int uu = 0; uu < S; uu++) {
        const float* pr = Pw + uu * RPAD;
        ulonglong2 r01 = *(const ulonglong2*)pr;
        ulonglong2 r23 = *(const ulonglong2*)(pr + 4);
        u64 r4 = *(const u64*)(pr + 8);
        unsigned ba = (mka >> uu) & 1u;
        unsigned bb = (mkb >> uu) & 1u;
        asm("{\n\t.reg .pred pa,pb;\n\t"
            "setp.ne.u32 pa,%10,0;\n\t"
            "setp.ne.u32 pb,%11,0;\n\t"
            "@pa add.rn.f32x2 %0,%0,%12;\n\t"
            "@pa add.rn.f32x2 %1,%1,%13;\n\t"
            "@pa add.rn.f32x2 %2,%2,%14;\n\t"
            "@pa add.rn.f32x2 %3,%3,%15;\n\t"
            "@pa add.rn.f32x2 %4,%4,%16;\n\t"
            "@pb add.rn.f32x2 %5,%5,%12;\n\t"
            "@pb add.rn.f32x2 %6,%6,%13;\n\t"
            "@pb add.rn.f32x2 %7,%7,%14;\n\t"
            "@pb add.rn.f32x2 %8,%8,%15;\n\t"
            "@pb add.rn.f32x2 %9,%9,%16;\n\t}"
            : "+l"(Aa0), "+l"(Aa1), "+l"(Aa2), "+l"(Aa3), "+l"(Aa4),
              "+l"(Ab0), "+l"(Ab1), "+l"(Ab2), "+l"(Ab3), "+l"(Ab4)
            : "r"(ba), "r"(bb),
              "l"(r01.x), "l"(r01.y), "l"(r23.x), "l"(r23.y), "l"(r4));
    }
    {
        u64 ca2 = pk(c1pa, c1pa);
        u64 cb2 = pk(c1pb, c1pb);
        ulonglong2 cq01 = *(const ulonglong2*)c2qw;
        ulonglong2 cq23 = *(const ulonglong2*)(c2qw + 4);
        u64 cq4 = *(const u64*)(c2qw + 8);
        ta[0] = f2add(ca2, cq01.x); tb[0] = f2add(cb2, cq01.x);
        ta[1] = f2add(ca2, cq01.y); tb[1] = f2add(cb2, cq01.y);
        ta[2] = f2add(ca2, cq23.x); tb[2] = f2add(cb2, cq23.x);
        ta[3] = f2add(ca2, cq23.y); tb[3] = f2add(cb2, cq23.y);
        ta[4] = f2add(ca2, cq4);    tb[4] = f2add(cb2, cq4);
    }
    float aav[M], abv[M];
    upk(aav[0], aav[1], Aa0); upk(aav[2], aav[3], Aa1); upk(aav[4], aav[5], Aa2);
    upk(aav[6], aav[7], Aa3); upk(aav[8], aav[9], Aa4);
    upk(abv[0], abv[1], Ab0); upk(abv[2], abv[3], Ab1); upk(abv[4], abv[5], Ab2);
    upk(abv[6], abv[7], Ab3); upk(abv[8], abv[9], Ab4);
#pragma unroll
    for (int v = 0; v < M; v++) {
        u64 ava2 = pk(aav[v], aav[v]);
        u64 avb2 = pk(abv[v], abv[v]);
        const float* c2r = C2w + v * RPAD;
        ulonglong2 c01 = *(const ulonglong2*)c2r;
        ulonglong2 c23 = *(const ulonglong2*)(c2r + 4);
        u64 c4 = *(const u64*)(c2r + 8);
        ta[0] = f2fma(ava2, c01.x, ta[0]); tb[0] = f2fma(avb2, c01.x, tb[0]);
        ta[1] = f2fma(ava2, c01.y, ta[1]); tb[1] = f2fma(avb2, c01.y, tb[1]);
        ta[2] = f2fma(ava2, c23.x, ta[2]); tb[2] = f2fma(avb2, c23.x, tb[2]);
        ta[3] = f2fma(ava2, c23.y, ta[3]); tb[3] = f2fma(avb2, c23.y, tb[3]);
        ta[4] = f2fma(ava2, c4,    ta[4]); tb[4] = f2fma(avb2, c4,    tb[4]);
    }
}

// 160 threads = 5 warps; warp ww serves templates 2ww (lanes 0-15) and 2ww+1 (lanes 16-31).
// Each lane owns rows ra=2*hl, rb=2*hl+1 (hl = lane % 16).
__global__ __launch_bounds__(160, 5)
void ltfgw_kernel(const int* __restrict__ edge_dst,
                  const float* __restrict__ C2g,
                  const float* __restrict__ alpha0,
                  float* __restrict__ out)
{
    __shared__ __align__(16) int   sNodes[S];
    __shared__ __align__(16) float sQ[RPAD];
    __shared__ __align__(16) float sC2[T][M][RPAD];    // holds -2*C2
    __shared__ __align__(16) float sC2q[T][RPAD];
    __shared__ __align__(16) float sOPC[T][RPAD];      // 1 + sum_b q[b]*(-2 C2[b][m])
    __shared__ __align__(16) float sP[T][S][RPAD];
    __shared__ __align__(16) float sKT[T][M][KTPAD];   // transposed K staging (per outer)
    __shared__ __align__(16) float sV[T][RPAD];
    __shared__ __align__(16) float sU[T][UPAD];

    const int n    = blockIdx.x;
    const int tid  = threadIdx.x;
    const int ww   = tid >> 5;
    const int lane = tid & 31;
    const int half = lane >> 4;
    const int hl   = lane & 15;
    const int t    = 2 * ww + half;
    const int ra   = 2 * hl;
    const int rb   = ra + 1;
    const bool aa  = (ra < S);   // hl <= 8
    const bool ab  = (rb < S);   // hl <= 7
    const bool vm  = (hl < M);

    if (tid < S) sNodes[tid] = (tid == 0) ? n : edge_dst[n * DEG + tid - 1];
    if (tid < RPAD) sQ[tid] = g_Q[tid];
    __syncthreads();

    // Precomputed masks: one aligned u64 per lane (slot 17 is zero)
    unsigned mka = 0u, mkb = 0u;
    if (aa) {
        u64 mk2 = *(const u64*)&g_MaskP[(long)n * MPAD + ra];
        mka = (unsigned)mk2;
        mkb = (unsigned)(mk2 >> 32);   // slot 17 prezeroed, so hl==8 is benign
    }

    // C2 staging: store -2*C2; compute sC2q and sOPC (per-(warp,half) private)
    if (vm) {
        float acc = 0.f;   // sum_b C2[m][b]^2 q[b]   (row m = hl)
        float acc2 = 0.f;  // sum_b q[b] * (-2 C2[b][hl])  (column hl)
#pragma unroll
        for (int r = 0; r < M; r++) {
            float c = __ldg(C2g + (t * M + r) * M + hl);   // C2[r][hl]
            sC2[t][r][hl] = -2.f * c;
            acc2 = fmaf(sQ[r], -2.f * c, acc2);
        }
#pragma unroll
        for (int b = 0; b < M; b++) {
            float c = __ldg(C2g + (t * M + hl) * M + b);   // C2[hl][b]
            acc = fmaf(c * c, sQ[b], acc);
        }
        sC2q[t][hl] = acc;
        sOPC[t][hl] = 1.f + acc2;
    }
    if (hl >= M && hl < RPAD) { sC2q[t][hl] = 0.f; sOPC[t][hl] = 0.f; }
    __syncwarp();

    const int nodea = aa ? sNodes[ra] : 0;
    const int nodeb = ab ? sNodes[rb] : 0;
    const int offa = (nodea * T + t) * RPAD;
    const int offb = (nodeb * T + t) * RPAD;
    const float nxa = aa ? __ldg(g_NX + nodea) : 0.f;
    const float nxb = ab ? __ldg(g_NX + nodeb) : 0.f;

    const float alpha = 1.f / (1.f + __expf(-__ldg(alpha0 + n)));
    const float a1c = 1.f - alpha;
    const float a2c = 2.f * alpha;
    const float p = 1.f / 17.f;
    const float c1pa = (float)__popc(mka) * (1.f / 17.f);
    const float c1pb = (float)__popc(mkb) * (1.f / 17.f);
    const float qm = vm ? sQ[hl] : 0.f;

    u64 K2a[5], K2b[5];
    u64 KT2[8]; float kt16 = 0.f;
#pragma unroll
    for (int j = 0; j < 8; j++) KT2[j] = 0;
    float ua = 0.f, ub = 0.f;

#pragma unroll 1
    for (int outer = 0; outer < N_OUTER; outer++) {
        u64 ta[5], tb[5];
        if (outer == 0) {
            // closed form from plan0 = p (x) q: tens0[r][m] = c1p_r * OPC[m] + C2q[m]
            u64 ca2 = pk(c1pa, c1pa);
            u64 cb2 = pk(c1pb, c1pb);
            ulonglong2 op01 = *(const ulonglong2*)&sOPC[t][0];
            ulonglong2 op23 = *(const ulonglong2*)&sOPC[t][4];
            u64 op4 = *(const u64*)&sOPC[t][8];
            ulonglong2 cq01 = *(const ulonglong2*)&sC2q[t][0];
            ulonglong2 cq23 = *(const ulonglong2*)&sC2q[t][4];
            u64 cq4 = *(const u64*)&sC2q[t][8];
            ta[0] = f2fma(ca2, op01.x, cq01.x); tb[0] = f2fma(cb2, op01.x, cq01.x);
            ta[1] = f2fma(ca2, op01.y, cq01.y); tb[1] = f2fma(cb2, op01.y, cq01.y);
            ta[2] = f2fma(ca2, op23.x, cq23.x); tb[2] = f2fma(cb2, op23.x, cq23.x);
            ta[3] = f2fma(ca2, op23.y, cq23.y); tb[3] = f2fma(cb2, op23.y, cq23.y);
            ta[4] = f2fma(ca2, op4,    cq4);    tb[4] = f2fma(cb2, op4,    cq4);
        } else {
            tens_pair(&sP[t][0][0], &sC2[t][0][0], &sC2q[t][0],
                      mka, mkb, c1pa, c1pb, ta, tb);
        }

        // G rows, eps from |G| mean over template, K = exp(-G/eps - mx)
        float Ga[M], Gb[M];
#pragma unroll
        for (int m = 0; m < M; m++) { Ga[m] = 0.f; Gb[m] = 0.f; }
        {
            u64 a1c2 = pk(a1c, a1c);
            u64 a2c2 = pk(a2c, a2c);
            if (aa) {
                u64 nxa2 = pk(nxa, nxa);
                ulonglong2 x01 = __ldg((const ulonglong2*)(g_XFP + offa));
                ulonglong2 x23 = __ldg((const ulonglong2*)(g_XFP + offa + 4));
                u64 x4 = __ldg((const u64*)(g_XFP + offa + 8));
                u64 g;
                g = f2fma(a2c2, ta[0], f2mul(a1c2, f2add(nxa2, x01.x))); upk(Ga[0], Ga[1], g);
                g = f2fma(a2c2, ta[1], f2mul(a1c2, f2add(nxa2, x01.y))); upk(Ga[2], Ga[3], g);
                g = f2fma(a2c2, ta[2], f2mul(a1c2, f2add(nxa2, x23.x))); upk(Ga[4], Ga[5], g);
                g = f2fma(a2c2, ta[3], f2mul(a1c2, f2add(nxa2, x23.y))); upk(Ga[6], Ga[7], g);
                g = f2fma(a2c2, ta[4], f2mul(a1c2, f2add(nxa2, x4)));    upk(Ga[8], Ga[9], g);
            }
            if (ab) {
                u64 nxb2 = pk(nxb, nxb);
                ulonglong2 x01 = __ldg((const ulonglong2*)(g_XFP + offb));
                ulonglong2 x23 = __ldg((const ulonglong2*)(g_XFP + offb + 4));
                u64 x4 = __ldg((const u64*)(g_XFP + offb + 8));
                u64 g;
                g = f2fma(a2c2, tb[0], f2mul(a1c2, f2add(nxb2, x01.x))); upk(Gb[0], Gb[1], g);
                g = f2fma(a2c2, tb[1], f2mul(a1c2, f2add(nxb2, x01.y))); upk(Gb[2], Gb[3], g);
                g = f2fma(a2c2, tb[2], f2mul(a1c2, f2add(nxb2, x23.x))); upk(Gb[4], Gb[5], g);
                g = f2fma(a2c2, tb[3], f2mul(a1c2, f2add(nxb2, x23.y))); upk(Gb[6], Gb[7], g);
                g = f2fma(a2c2, tb[4], f2mul(a1c2, f2add(nxb2, x4)));    upk(Gb[8], Gb[9], g);
            }
        }
        float asum = 0.f;
#pragma unroll
        for (int m = 0; m < M; m++) asum += fabsf(Ga[m]) + fabsf(Gb[m]);
#pragma unroll
        for (int o = 8; o; o >>= 1) asum += __shfl_xor_sync(0xffffffffu, asum, o);
        float eps = 0.05f * asum * (1.f / 170.f) + 1e-8f;
        float nie = -__fdividef(1.f, eps);
        float mx = -1e30f;
#pragma unroll
        for (int m = 0; m < M; m++) {
            Ga[m] *= nie; Gb[m] *= nie;
            if (aa) mx = fmaxf(mx, Ga[m]);
            if (ab) mx = fmaxf(mx, Gb[m]);
        }
#pragma unroll
        for (int o = 8; o; o >>= 1) mx = fmaxf(mx, __shfl_xor_sync(0xffffffffu, mx, o));
        // K rows + transposed staging store (one STS.64 per m)
        {
            float Ksa[M], Ksb[M];
#pragma unroll
            for (int m = 0; m < M; m++) {
                Ksa[m] = aa ? __expf(Ga[m] - mx) : 0.f;
                Ksb[m] = ab ? __expf(Gb[m] - mx) : 0.f;
            }
#pragma unroll
            for (int j = 0; j < 5; j++) {
                K2a[j] = pk(Ksa[2 * j], Ksa[2 * j + 1]);
                K2b[j] = pk(Ksb[2 * j], Ksb[2 * j + 1]);
            }
            if (aa) {
#pragma unroll
                for (int m = 0; m < M; m++)
                    *(u64*)&sKT[t][m][ra] = pk(Ksa[m], Ksb[m]);
            }
        }
        if (hl < RPAD) sV[t][hl] = (hl < M) ? 1.f : 0.f;
        __syncwarp();
        // Gather KT column into registers (once per outer; conflict-free 144B stride)
        if (vm) {
            ulonglong2 k01 = *(const ulonglong2*)&sKT[t][hl][0];
            ulonglong2 k23 = *(const ulonglong2*)&sKT[t][hl][4];
            ulonglong2 k45 = *(const ulonglong2*)&sKT[t][hl][8];
            ulonglong2 k67 = *(const ulonglong2*)&sKT[t][hl][12];
            KT2[0] = k01.x; KT2[1] = k01.y; KT2[2] = k23.x; KT2[3] = k23.y;
            KT2[4] = k45.x; KT2[5] = k45.y; KT2[6] = k67.x; KT2[7] = k67.y;
            kt16 = sKT[t][hl][16];
        }
        __syncwarp();

        // u-step helper (row sums against current sV)
        auto ustep = [&]() {
            ulonglong2 va = *(const ulonglong2*)&sV[t][0];
            ulonglong2 vb = *(const ulonglong2*)&sV[t][4];
            u64 vc = *(const u64*)&sV[t][8];
            u64 ca0 = f2mul(K2a[0], va.x);
            u64 ca1 = f2mul(K2a[1], va.y);
            ca0 = f2fma(K2a[2], vb.x, ca0);
            ca1 = f2fma(K2a[3], vb.y, ca1);
            ca0 = f2fma(K2a[4], vc, ca0);
            u64 acca = f2add(ca0, ca1);
            u64 cb0 = f2mul(K2b[0], va.x);
            u64 cb1 = f2mul(K2b[1], va.y);
            cb0 = f2fma(K2b[2], vb.x, cb0);
            cb1 = f2fma(K2b[3], vb.y, cb1);
            cb0 = f2fma(K2b[4], vc, cb0);
            u64 accb = f2add(cb0, cb1);
            float la, ha, lb, hb;
            upk(la, ha, acca); upk(lb, hb, accb);
            ua = __fdividef(p, fmaxf(la + ha, 1e-35f));
            ub = __fdividef(p, fmaxf(lb + hb, 1e-35f));
        };

        // Sinkhorn: runtime loop (15 u,v iterations) + peeled final u-step
#pragma unroll 1
        for (int it = 0; it < N_SINK; it++) {
            ustep();
            if (hl < 9) *(u64*)&sU[t][ra] = pk(ua, ub);
            __syncwarp();
            if (vm) {
                ulonglong2 u01 = *(const ulonglong2*)&sU[t][0];
                ulonglong2 u23 = *(const ulonglong2*)&sU[t][4];
                ulonglong2 u45 = *(const ulonglong2*)&sU[t][8];
                ulonglong2 u67 = *(const ulonglong2*)&sU[t][12];
                float u16 = sU[t][16];
                u64 c0 = f2mul(KT2[0], u01.x);
                u64 c1 = f2mul(KT2[1], u01.y);
                u64 c2 = f2mul(KT2[2], u23.x);
                c0 = f2fma(KT2[3], u23.y, c0);
                c1 = f2fma(KT2[4], u45.x, c1);
                c2 = f2fma(KT2[5], u45.y, c2);
                c0 = f2fma(KT2[6], u67.x, c0);
                c1 = f2fma(KT2[7], u67.y, c1);
                u64 a2 = f2add(f2add(c0, c1), c2);
                float clo, chi; upk(clo, chi, a2);
                float cs = (clo + chi) + kt16 * u16;
                sV[t][hl] = __fdividef(qm, fmaxf(cs, 1e-35f));
            }
            __syncwarp();
        }
        ustep();

        // plan = u (.) K (.) v   (reload v from sV)
        {
            ulonglong2 va = *(const ulonglong2*)&sV[t][0];
            ulonglong2 vb = *(const ulonglong2*)&sV[t][4];
            u64 vc = *(const u64*)&sV[t][8];
            if (aa) {
                u64 ua2 = pk(ua, ua);
                ulonglong2 o;
                o.x = f2mul(f2mul(ua2, K2a[0]), va.x);
                o.y = f2mul(f2mul(ua2, K2a[1]), va.y);
                *(ulonglong2*)&sP[t][ra][0] = o;
                ulonglong2 o2;
                o2.x = f2mul(f2mul(ua2, K2a[2]), vb.x);
                o2.y = f2mul(f2mul(ua2, K2a[3]), vb.y);
                *(ulonglong2*)&sP[t][ra][4] = o2;
                *(u64*)&sP[t][ra][8] = f2mul(f2mul(ua2, K2a[4]), vc);
            }
            if (ab) {
                u64 ub2 = pk(ub, ub);
                ulonglong2 o;
                o.x = f2mul(f2mul(ub2, K2b[0]), va.x);
                o.y = f2mul(f2mul(ub2, K2b[1]), va.y);
                *(ulonglong2*)&sP[t][rb][0] = o;
                ulonglong2 o2;
                o2.x = f2mul(f2mul(ub2, K2b[2]), vb.x);
                o2.y = f2mul(f2mul(ub2, K2b[3]), vb.y);
                *(ulonglong2*)&sP[t][rb][4] = o2;
                *(u64*)&sP[t][rb][8] = f2mul(f2mul(ub2, K2b[4]), vc);
            }
        }
        __syncwarp();
    }

    // final tens + contractions (v reloaded from sV; plan rows already in sP)
    u64 ta[5], tb[5];
    tens_pair(&sP[t][0][0], &sC2[t][0][0], &sC2q[t][0],
              mka, mkb, c1pa, c1pb, ta, tb);

    u64 lin2 = 0, gw2 = 0;
    {
        ulonglong2 va = *(const ulonglong2*)&sV[t][0];
        ulonglong2 vb = *(const ulonglong2*)&sV[t][4];
        u64 vc = *(const u64*)&sV[t][8];
        u64 vs[5] = { va.x, va.y, vb.x, vb.y, vc };
        if (aa) {
            u64 ua2 = pk(ua, ua);
            u64 nxa2 = pk(nxa, nxa);
            ulonglong2 x01 = __ldg((const ulonglong2*)(g_XFP + offa));
            ulonglong2 x23 = __ldg((const ulonglong2*)(g_XFP + offa + 4));
            u64 x4 = __ldg((const u64*)(g_XFP + offa + 8));
            u64 xs[5] = { x01.x, x01.y, x23.x, x23.y, x4 };
#pragma unroll
            for (int j = 0; j < 5; j++) {
                u64 pl = f2mul(f2mul(ua2, K2a[j]), vs[j]);
                lin2 = f2fma(f2add(nxa2, xs[j]), pl, lin2);
                gw2  = f2fma(ta[j], pl, gw2);
            }
        }
        if (ab) {
            u64 ub2 = pk(ub, ub);
            u64 nxb2 = pk(nxb, nxb);
            ulonglong2 x01 = __ldg((const ulonglong2*)(g_XFP + offb));
            ulonglong2 x23 = __ldg((const ulonglong2*)(g_XFP + offb + 4));
            u64 x4 = __ldg((const u64*)(g_XFP + offb + 8));
            u64 xs[5] = { x01.x, x01.y, x23.x, x23.y, x4 };
#pragma unroll
            for (int j = 0; j < 5; j++) {
                u64 pl = f2mul(f2mul(ub2, K2b[j]), vs[j]);
                lin2 = f2fma(f2add(nxb2, xs[j]), pl, lin2);
                gw2  = f2fma(tb[j], pl, gw2);
            }
        }
    }
    float llo, lhi, glo, ghi;
    upk(llo, lhi, lin2);
    upk(glo, ghi, gw2);
    float lin = llo + lhi, gw = glo + ghi;
#pragma unroll
    for (int o = 8; o; o >>= 1) {
        lin += __shfl_xor_sync(0xffffffffu, lin, o);
        gw  += __shfl_xor_sync(0xffffffffu, gw, o);
    }
    if (hl == 0)
        out[n * T + t] = a1c * lin + alpha * gw;
}

extern "C" void kernel_launch(void* const* d_in, const int* in_sizes, int n_in,
                              void* d_out, int out_size)
{
    const float* x      = (const float*)d_in[0];
    const int*   ei     = (const int*)d_in[1];
    const float* C2g    = (const float*)d_in[2];
    const float* F2g    = (const float*)d_in[3];
    const float* q0     = (const float*)d_in[4];
    const float* alpha0 = (const float*)d_in[5];
    float* out = (float*)d_out;

    const int* edge_dst = ei + NNODES * DEG;

    xf2_kernel<<<NNODES / 4, 128>>>(x, F2g, q0);
    mask_kernel<<<(NNODES * 32 + 255) / 256, 256>>>(edge_dst);
    ltfgw_kernel<<<NNODES, 160>>>(edge_dst, C2g, alpha0, out);
}